// round 15
// baseline (speedup 1.0000x reference)
#include <cuda_runtime.h>

#define BATCH   256
#define INDIM   159
#define MDIM    93
#define MATEL   2976
#define LINDIM  (MDIM + MATEL)   /* 3069 */
#define KPATH   64
#define SIGDIM  340

typedef unsigned long long u64;

__device__ float g_lin2[2][BATCH * LINDIM];   // split-K partials
__device__ float g_newV[BATCH * MDIM * KPATH];
__device__ float g_lgt[4 * BATCH * 10];
__device__ int   g_cnt[BATCH];                // zero-init; restored each run

// ---------------- packed f32x2 helpers --------------------------------------
__device__ __forceinline__ u64 bc2(float x) {
    u64 r; asm("mov.b64 %0, {%1, %1};" : "=l"(r) : "f"(x)); return r;
}
__device__ __forceinline__ void unpk2(u64 p, float& lo, float& hi) {
    asm("mov.b64 {%0, %1}, %2;" : "=f"(lo), "=f"(hi) : "l"(p));
}
__device__ __forceinline__ u64 fma2(u64 a, u64 b, u64 c) {
    u64 d; asm("fma.rn.f32x2 %0, %1, %2, %3;" : "=l"(d) : "l"(a), "l"(b), "l"(c)); return d;
}

// ---------------------------------------------------------------------------
// Kernel 1: lin partial = x @ W^T (split-K over input dim) + bias (split 0).
// ---------------------------------------------------------------------------
__global__ void __launch_bounds__(256) k_linear(
    const float* __restrict__ x,
    const float* __restrict__ Wm, const float* __restrict__ bm,
    const float* __restrict__ Wc, const float* __restrict__ bc)
{
    __shared__ float xt[80][32];        // transposed x tile for this split
    __shared__ float Ws[128][33];
    const int tid = threadIdx.x;
    const int b0  = blockIdx.y * 32;
    const int r0  = blockIdx.x * 128;
    const int sp  = blockIdx.z;
    const int ct_lo = sp ? 80 : 0;
    const int ct_hi = sp ? INDIM : 80;

    const int rowt = tid & 63;          // row pair: rowt, rowt+64
    const int bpt  = tid >> 6;          // 0..3 -> batch pairs 4*bpt+i

    for (int e = tid; e < (ct_hi - ct_lo) * 32; e += 256) {
        int c = e >> 5, bb = e & 31;
        xt[c][bb] = x[(b0 + bb) * INDIM + ct_lo + c];
    }

    u64 acc2[2][4];
#pragma unroll
    for (int j = 0; j < 2; j++) {
        const int rg = r0 + rowt + 64 * j;
        float bias = 0.f;
        if (sp == 0 && rg < LINDIM) bias = (rg < MDIM) ? bm[rg] : bc[rg - MDIM];
        const u64 bb2 = bc2(bias);
#pragma unroll
        for (int i = 0; i < 4; i++) acc2[j][i] = bb2;
    }

    for (int ct = ct_lo; ct < ct_hi; ct += 32) {
        const int cn = min(32, ct_hi - ct);
        __syncthreads();
        for (int e = tid; e < 128 * 32; e += 256) {
            int rr = e >> 5, cc = e & 31;
            int rg = r0 + rr;
            float w = 0.f;
            if (rg < LINDIM && cc < cn)
                w = (rg < MDIM) ? Wm[rg * INDIM + ct + cc]
                                : Wc[(rg - MDIM) * INDIM + ct + cc];
            Ws[rr][cc] = w;
        }
        __syncthreads();
        for (int cc = 0; cc < cn; cc++) {
            u64 w2[2], xp[4];
#pragma unroll
            for (int j = 0; j < 2; j++) w2[j] = bc2(Ws[rowt + 64 * j][cc]);
#pragma unroll
            for (int i = 0; i < 4; i++)
                xp[i] = *(const u64*)&xt[ct - ct_lo + cc][2 * (4 * bpt + i)];
#pragma unroll
            for (int j = 0; j < 2; j++)
#pragma unroll
                for (int i = 0; i < 4; i++)
                    acc2[j][i] = fma2(w2[j], xp[i], acc2[j][i]);
        }
    }
#pragma unroll
    for (int j = 0; j < 2; j++) {
        const int rg = r0 + rowt + 64 * j;
        if (rg < LINDIM) {
#pragma unroll
            for (int i = 0; i < 4; i++) {
                float lo, hi; unpk2(acc2[j][i], lo, hi);
                const int p = 4 * bpt + i;
                g_lin2[sp][(b0 + 2 * p) * LINDIM + rg]     = lo;
                g_lin2[sp][(b0 + 2 * p + 1) * LINDIM + rg] = hi;
            }
        }
    }
}

// ---------------------------------------------------------------------------
// Kernel 2: newV[b,i,k] = mean + band(M) @ eps   (all 64 k per block).
// One block per batch; 256 thr; f32x2 over k-pairs (tid&31 = k-pair).
// ---------------------------------------------------------------------------
__global__ void __launch_bounds__(256) k_newv(const float* __restrict__ eps)
{
    __shared__ float eps_s[MDIM * KPATH];   // 23808 B
    __shared__ float covm[LINDIM];          // 12276 B
    const int b = blockIdx.x, tid = threadIdx.x;

    for (int e = tid; e < MDIM * KPATH; e += 256)
        eps_s[e] = eps[b * MDIM * KPATH + e];
    for (int e = tid; e < LINDIM; e += 256)
        covm[e] = g_lin2[0][b * LINDIM + e] + g_lin2[1][b * LINDIM + e];
    __syncthreads();

    const int kp = tid & 31;        // k-pair 0..31
    const int ig = tid >> 5;        // 0..7
    for (int i = ig; i < MDIM; i += 8) {
        const int X = i / 3, tr = i % 3;
        const int tbase = 93 + tr * (tr + 1) / 2;
        u64 acc = bc2(covm[i]);
        for (int y = 0; y <= X; y++) {
            const int d = X - y;
            const int blk6 = (31 * d - (d * (d - 1)) / 2 + y) * 6 + tbase;
#pragma unroll
            for (int tc = 0; tc < 3; tc++) {
                if (tc <= tr) {
                    const u64 ep = *(const u64*)&eps_s[(y * 3 + tc) * KPATH + 2 * kp];
                    acc = fma2(bc2(covm[blk6 + tc]), ep, acc);
                }
            }
        }
        *(u64*)&g_newV[(b * MDIM + i) * KPATH + 2 * kp] = acc;
    }
}

// ---------------------------------------------------------------------------
// Kernel 3 (slim): signatures + normalization + logits + softmax ONLY.
// 64 thr/block, 16 paths (quarter of K), grid 4*BATCH = 1024.
// smem just xs + nvs (~6.6KB) -> 8 blocks/SM (reg cap 128), ONE wave.
// 4 lanes/path, lane owns leading index a; pure scalar state (85 floats).
// ---------------------------------------------------------------------------
__global__ void __launch_bounds__(64, 8) k_sigf(
    const float* __restrict__ x,
    const float* __restrict__ Wf, const float* __restrict__ bf,
    float* __restrict__ out)
{
    __shared__ float xs[INDIM];
    __shared__ float nvs[MDIM * 16];
    __shared__ float red[2 * SIGDIM];
    __shared__ int   arrive_s;

    const int blk = blockIdx.x;
    const int b = blk >> 2, q = blk & 3;    // quarter of K
    const int tid = threadIdx.x;

    for (int e = tid; e < INDIM; e += 64) xs[e] = x[b * INDIM + e];
    for (int e = tid; e < MDIM * 16; e += 64) {
        int j = e >> 4, kk = e & 15;
        nvs[e] = g_newV[(b * MDIM + j) * KPATH + q * 16 + kk];
    }
    __syncthreads();

    // ---- signature recursion: 4 lanes/path, scalar state ----
    const int pk = tid >> 2;        // path 0..15
    const int a  = tid & 3;         // leading tensor index

    float S1a = 0.f;
    float S2a[4], S3a[16], S4a[64];
#pragma unroll
    for (int i = 0; i < 4; i++)  S2a[i] = 0.f;
#pragma unroll
    for (int i = 0; i < 16; i++) S3a[i] = 0.f;
#pragma unroll
    for (int i = 0; i < 64; i++) S4a[i] = 0.f;

    float p0 = xs[0], p1 = xs[1], p2 = xs[2], p3 = xs[96];
    float q0 = nvs[0 * 16 + pk], q1 = nvs[1 * 16 + pk], q2 = nvs[2 * 16 + pk];
    float qt = xs[128];
    for (int m = 0; m < 31; m++) {
#pragma unroll
        for (int half = 0; half < 2; half++) {
            float d0, d1, d2, d3;
            if (half == 0) {
                d0 = q0 - p0; d1 = q1 - p1; d2 = q2 - p2; d3 = qt - p3;
                // prefetch old m+1
                p0 = xs[3 * (m + 1) + 0];
                p1 = xs[3 * (m + 1) + 1];
                p2 = xs[3 * (m + 1) + 2];
                p3 = xs[96 + m + 1];
            } else {
                d0 = p0 - q0; d1 = p1 - q1; d2 = p2 - q2; d3 = p3 - qt;
                if (m < 30) {   // prefetch new m+1
                    q0 = nvs[(3 * m + 3) * 16 + pk];
                    q1 = nvs[(3 * m + 4) * 16 + pk];
                    q2 = nvs[(3 * m + 5) * 16 + pk];
                    qt = xs[128 + m + 1];
                }
            }
            const float dd[4] = { d0, d1, d2, d3 };
            const float da = (a & 2) ? ((a & 1) ? d3 : d2) : ((a & 1) ? d1 : d0);

            const float hh[4] = { 0.5f * d0, 0.5f * d1, 0.5f * d2, 0.5f * d3 };

            // level 4: S4[bq][c][e] += (S3[bq][c] + r[bq]*hd[c]) * d[e]
            const float g4 = fmaf(0.25f, da, S1a) * (1.f / 3.f);
            float r[4];
#pragma unroll
            for (int bq = 0; bq < 4; bq++) r[bq] = fmaf(g4, dd[bq], S2a[bq]);
#pragma unroll
            for (int bq = 0; bq < 4; bq++) {
#pragma unroll
                for (int c = 0; c < 4; c++) {
                    const float t = fmaf(r[bq], hh[c], S3a[bq * 4 + c]);
                    S4a[(bq * 4 + c) * 4 + 0] = fmaf(t, d0, S4a[(bq * 4 + c) * 4 + 0]);
                    S4a[(bq * 4 + c) * 4 + 1] = fmaf(t, d1, S4a[(bq * 4 + c) * 4 + 1]);
                    S4a[(bq * 4 + c) * 4 + 2] = fmaf(t, d2, S4a[(bq * 4 + c) * 4 + 2]);
                    S4a[(bq * 4 + c) * 4 + 3] = fmaf(t, d3, S4a[(bq * 4 + c) * 4 + 3]);
                }
            }
            // level 3: S3[bq][c] += (S2[bq] + g3h*d[bq]) * d[c]
            const float g3h = 0.5f * fmaf(1.f / 3.f, da, S1a);
            float w3[4];
#pragma unroll
            for (int bq = 0; bq < 4; bq++) w3[bq] = fmaf(g3h, dd[bq], S2a[bq]);
#pragma unroll
            for (int bq = 0; bq < 4; bq++) {
                S3a[bq * 4 + 0] = fmaf(w3[bq], d0, S3a[bq * 4 + 0]);
                S3a[bq * 4 + 1] = fmaf(w3[bq], d1, S3a[bq * 4 + 1]);
                S3a[bq * 4 + 2] = fmaf(w3[bq], d2, S3a[bq * 4 + 2]);
                S3a[bq * 4 + 3] = fmaf(w3[bq], d3, S3a[bq * 4 + 3]);
            }
            // level 2 / 1
            const float g2 = fmaf(0.5f, da, S1a);
#pragma unroll
            for (int bq = 0; bq < 4; bq++) S2a[bq] = fmaf(g2, dd[bq], S2a[bq]);
            S1a += da;
        }
    }

    // ---- per-path norms (4 lanes hold complementary slices) ----
    float n1 = S1a * S1a;
    float n2 = 0.f, n3 = 0.f, n4 = 0.f;
#pragma unroll
    for (int i = 0; i < 4; i++)  n2 = fmaf(S2a[i], S2a[i], n2);
#pragma unroll
    for (int i = 0; i < 16; i++) n3 = fmaf(S3a[i], S3a[i], n3);
#pragma unroll
    for (int i = 0; i < 64; i++) n4 = fmaf(S4a[i], S4a[i], n4);
#pragma unroll
    for (int msk = 1; msk <= 2; msk <<= 1) {
        n1 += __shfl_xor_sync(0xffffffffu, n1, msk);
        n2 += __shfl_xor_sync(0xffffffffu, n2, msk);
        n3 += __shfl_xor_sync(0xffffffffu, n3, msk);
        n4 += __shfl_xor_sync(0xffffffffu, n4, msk);
    }
    const float norm2 = 1.f + n1 + n2 + n3 + n4;
    const float psi = (norm2 <= 4.f) ? norm2 : (8.f - 16.f / norm2);
    float lo_ = 0.f, hi_ = 1.f;
    for (int it = 0; it < 30; it++) {
        float mid = 0.5f * (lo_ + hi_);
        float m2 = mid * mid, m4 = m2 * m2;
        float val = 1.f + m2 * n1 + m4 * n2 + (m4 * m2) * n3 + (m4 * m4) * n4;
        bool pos = val > psi;
        hi_ = pos ? mid : hi_;
        lo_ = pos ? lo_ : mid;
    }
    const float lam = 0.5f * (lo_ + hi_);
    const float l2 = lam * lam, l3 = l2 * lam, l4 = l2 * l2;
    S1a *= lam;
#pragma unroll
    for (int i = 0; i < 4; i++)  S2a[i] *= l2;
#pragma unroll
    for (int i = 0; i < 16; i++) S3a[i] *= l3;
#pragma unroll
    for (int i = 0; i < 64; i++) S4a[i] *= l4;

    // ---- reduce the 8 paths of each warp; lanes 0..3 hold slice sums ----
    const int w = tid >> 5;
    const int lane = tid & 31;
#define WRED(v) do { \
        (v) += __shfl_down_sync(0xffffffffu, (v), 16); \
        (v) += __shfl_down_sync(0xffffffffu, (v), 8);  \
        (v) += __shfl_down_sync(0xffffffffu, (v), 4);  \
    } while (0)
    {
        float v = S1a; WRED(v);
        if (lane < 4) red[w * SIGDIM + a] = v;
    }
#pragma unroll
    for (int i = 0; i < 4; i++) {
        float v = S2a[i]; WRED(v);
        if (lane < 4) red[w * SIGDIM + 4 + a * 4 + i] = v;
    }
#pragma unroll
    for (int i = 0; i < 16; i++) {
        float v = S3a[i]; WRED(v);
        if (lane < 4) red[w * SIGDIM + 20 + a * 16 + i] = v;
    }
#pragma unroll
    for (int i = 0; i < 64; i++) {
        float v = S4a[i]; WRED(v);
        if (lane < 4) red[w * SIGDIM + 84 + a * 64 + i] = v;
    }
#undef WRED
    __syncthreads();
    for (int e = tid; e < SIGDIM; e += 64)
        red[e] = red[e] + red[SIGDIM + e];
    __syncthreads();

    // ---- partial logits for this quarter-batch ----
    for (int c = w; c < 10; c += 2) {
        float acc = 0.f;
        for (int sidx = lane; sidx < SIGDIM; sidx += 32)
            acc = fmaf(red[sidx], Wf[c * SIGDIM + sidx], acc);
#pragma unroll
        for (int off = 16; off >= 1; off >>= 1)
            acc += __shfl_xor_sync(0xffffffffu, acc, off);
        if (lane == 0) g_lgt[blk * 10 + c] = acc;
    }
    __syncthreads();

    // ---- arrival counter: 4th block for this b does the softmax ----
    if (tid == 0) {
        __threadfence();
        arrive_s = atomicAdd(&g_cnt[b], 1);
    }
    __syncthreads();
    if (arrive_s == 3 && w == 0) {
        __threadfence();
        float v = -3.0e38f;
        if (lane < 10) {
            float sum = g_lgt[(4 * b) * 10 + lane] + g_lgt[(4 * b + 1) * 10 + lane]
                      + g_lgt[(4 * b + 2) * 10 + lane] + g_lgt[(4 * b + 3) * 10 + lane];
            v = sum * (1.f / 64.f) + bf[lane];
        }
        float mx = v;
#pragma unroll
        for (int off = 16; off >= 1; off >>= 1)
            mx = fmaxf(mx, __shfl_xor_sync(0xffffffffu, mx, off));
        float ex = (lane < 10) ? expf(v - mx) : 0.f;
        float se = ex;
#pragma unroll
        for (int off = 16; off >= 1; off >>= 1)
            se += __shfl_xor_sync(0xffffffffu, se, off);
        const float lse = mx + logf(se);
        if (lane < 10) out[b * 10 + lane] = v - lse;
        if (lane == 0) g_cnt[b] = 0;   // restore for next graph replay
    }
}

// ---------------------------------------------------------------------------
extern "C" void kernel_launch(void* const* d_in, const int* in_sizes, int n_in,
                              void* d_out, int out_size)
{
    const float* x   = (const float*)d_in[0];
    const float* Wm  = (const float*)d_in[1];
    const float* bm  = (const float*)d_in[2];
    const float* Wc  = (const float*)d_in[3];
    const float* bc  = (const float*)d_in[4];
    const float* Wf  = (const float*)d_in[5];
    const float* bf  = (const float*)d_in[6];
    const float* eps = (const float*)d_in[7];
    float* out = (float*)d_out;

    k_linear<<<dim3(24, 8, 2), 256>>>(x, Wm, bm, Wc, bc);
    k_newv<<<BATCH, 256>>>(eps);
    k_sigf<<<4 * BATCH, 64>>>(x, Wf, bf, out);
}